// round 3
// baseline (speedup 1.0000x reference)
#include <cuda_runtime.h>
#include <cuda_fp16.h>

#define N_X   20000
#define N_ELL 48
#define N_K   1024
#define N_TAU 600

#define N_CHUNK 12
#define T_PER_CHUNK (N_TAU / N_CHUNK)   // 50
#define K_PER_BLOCK 16
#define NG 12                            // ell groups of 4

// Scratch partial sums: [chunk][ell][k]
__device__ float g_Tl[N_CHUNK][N_ELL][N_K];
__device__ float g_El[N_CHUNK][N_ELL][N_K];

// Packed fp16 tables: row i0, group g -> 16 halves (p0 x4, p1 x4, p2 x4, pe x4)
// row stride = 24 uint4 (384 B)
__device__ uint4 g_pack[N_X * 24];

__device__ __forceinline__ unsigned h2u(__half2 h) {
    return *reinterpret_cast<unsigned*>(&h);
}
__device__ __forceinline__ __half2 u2h(unsigned u) {
    __half2 h; *reinterpret_cast<unsigned*>(&h) = u; return h;
}

// ---------------------------------------------------------------------------
// Kernel 0: pack 4 float tables -> interleaved fp16.
// ---------------------------------------------------------------------------
__global__ __launch_bounds__(256) void pack_tables(
    const float* __restrict__ p0t, const float* __restrict__ p1t,
    const float* __restrict__ p2t, const float* __restrict__ pet)
{
    const int tid = blockIdx.x * 256 + threadIdx.x;   // 0 .. N_X*12-1
    if (tid >= N_X * NG) return;
    const float4* __restrict__ P0 = (const float4*)p0t;
    const float4* __restrict__ P1 = (const float4*)p1t;
    const float4* __restrict__ P2 = (const float4*)p2t;
    const float4* __restrict__ PE = (const float4*)pet;
    const float4 v0 = P0[tid], v1 = P1[tid], v2 = P2[tid], ve = PE[tid];

    uint4 oA, oB;
    oA.x = h2u(__float22half2_rn(make_float2(v0.x, v0.y)));
    oA.y = h2u(__float22half2_rn(make_float2(v0.z, v0.w)));
    oA.z = h2u(__float22half2_rn(make_float2(v1.x, v1.y)));
    oA.w = h2u(__float22half2_rn(make_float2(v1.z, v1.w)));
    oB.x = h2u(__float22half2_rn(make_float2(v2.x, v2.y)));
    oB.y = h2u(__float22half2_rn(make_float2(v2.z, v2.w)));
    oB.z = h2u(__float22half2_rn(make_float2(ve.x, ve.y)));
    oB.w = h2u(__float22half2_rn(make_float2(ve.z, ve.w)));
    g_pack[tid * 2]     = oA;
    g_pack[tid * 2 + 1] = oB;
}

// ---------------------------------------------------------------------------
// Kernel 1: fused interpolation + source product + tau-trapezoid partials.
// block (12,16), grid (64 k-blocks, 12 tau-chunks).
// Stage: per (k,t) precompute i0, w, and wt-premultiplied sources into smem.
// ---------------------------------------------------------------------------
__global__ __launch_bounds__(192) void spectrum_k1(
    const float* __restrict__ kk_arr,
    const float* __restrict__ tau,
    const float* __restrict__ tau0p,
    const float* __restrict__ S0,
    const float* __restrict__ S1,
    const float* __restrict__ S2,
    const float* __restrict__ SE,
    const float* __restrict__ bx)
{
    __shared__ int    sh_i0[T_PER_CHUNK][K_PER_BLOCK];
    __shared__ float  sh_wq[T_PER_CHUNK][K_PER_BLOCK];
    __shared__ float4 sh_s [T_PER_CHUNK][K_PER_BLOCK];

    const int chunk = blockIdx.y;
    const int t0    = chunk * T_PER_CHUNK;
    const int kbase = blockIdx.x * K_PER_BLOCK;
    const int tid   = threadIdx.y * NG + threadIdx.x;

    const float tau0 = tau0p[0];
    const float xmin = bx[0];
    const float xmax = bx[N_X - 1];
    const float sc   = (float)(N_X - 1) / (xmax - xmin);

    // Staging: entry -> (kcol = e / T, t = e % T) so S loads walk t (coalesced).
    for (int e = tid; e < K_PER_BLOCK * T_PER_CHUNK; e += 192) {
        const int kcol = e / T_PER_CHUNK;
        const int t    = e - kcol * T_PER_CHUNK;
        const int tg   = t0 + t;
        const int kidx = kbase + kcol;
        const float kval = kk_arr[kidx];

        const float wl = (tg == 0)         ? 0.0f : (tau[tg] - tau[tg - 1]);
        const float wr = (tg == N_TAU - 1) ? 0.0f : (tau[tg + 1] - tau[tg]);
        const float wt = 0.5f * (wl + wr);

        const float x = kval * (tau0 - tau[tg]);
        float pos = (x - xmin) * sc;
        pos = fminf(fmaxf(pos, 0.0f), (float)(N_X - 1));
        int i0 = (int)pos;
        if (i0 > N_X - 2) i0 = N_X - 2;

        const int sidx = kidx * N_TAU + tg;
        sh_i0[t][kcol] = i0 * 24;
        sh_wq[t][kcol] = pos - (float)i0;
        sh_s [t][kcol] = make_float4(S0[sidx] * wt, S1[sidx] * wt,
                                     S2[sidx] * wt, SE[sidx] * wt);
    }
    __syncthreads();

    const int kcol = threadIdx.y;
    const int g2   = threadIdx.x * 2;

    float aT0 = 0.f, aT1 = 0.f, aT2 = 0.f, aT3 = 0.f;
    float aE0 = 0.f, aE1 = 0.f, aE2 = 0.f, aE3 = 0.f;

    const uint4* __restrict__ TP = g_pack;

    #pragma unroll 5
    for (int t = 0; t < T_PER_CHUNK; ++t) {
        const int    ra = sh_i0[t][kcol] + g2;
        const float  w  = sh_wq[t][kcol];
        const float4 s  = sh_s[t][kcol];

        const uint4 A0 = TP[ra],      A1 = TP[ra + 1];
        const uint4 B0 = TP[ra + 24], B1 = TP[ra + 25];

        const __half2 w2 = __float2half2_rn(w);
        const __half2 h0a = __hfma2(w2, __hsub2(u2h(B0.x), u2h(A0.x)), u2h(A0.x));
        const __half2 h0b = __hfma2(w2, __hsub2(u2h(B0.y), u2h(A0.y)), u2h(A0.y));
        const __half2 h1a = __hfma2(w2, __hsub2(u2h(B0.z), u2h(A0.z)), u2h(A0.z));
        const __half2 h1b = __hfma2(w2, __hsub2(u2h(B0.w), u2h(A0.w)), u2h(A0.w));
        const __half2 h2a = __hfma2(w2, __hsub2(u2h(B1.x), u2h(A1.x)), u2h(A1.x));
        const __half2 h2b = __hfma2(w2, __hsub2(u2h(B1.y), u2h(A1.y)), u2h(A1.y));
        const __half2 hea = __hfma2(w2, __hsub2(u2h(B1.z), u2h(A1.z)), u2h(A1.z));
        const __half2 heb = __hfma2(w2, __hsub2(u2h(B1.w), u2h(A1.w)), u2h(A1.w));

        const float2 f0a = __half22float2(h0a);
        const float2 f0b = __half22float2(h0b);
        const float2 f1a = __half22float2(h1a);
        const float2 f1b = __half22float2(h1b);
        const float2 f2a = __half22float2(h2a);
        const float2 f2b = __half22float2(h2b);
        const float2 fea = __half22float2(hea);
        const float2 feb = __half22float2(heb);

        aT0 += s.x * f0a.x + s.y * f1a.x + s.z * f2a.x;
        aT1 += s.x * f0a.y + s.y * f1a.y + s.z * f2a.y;
        aT2 += s.x * f0b.x + s.y * f1b.x + s.z * f2b.x;
        aT3 += s.x * f0b.y + s.y * f1b.y + s.z * f2b.y;
        aE0 += s.w * fea.x;
        aE1 += s.w * fea.y;
        aE2 += s.w * feb.x;
        aE3 += s.w * feb.y;
    }

    const int ell  = 4 * threadIdx.x;
    const int kidx = kbase + kcol;
    g_Tl[chunk][ell + 0][kidx] = aT0;
    g_Tl[chunk][ell + 1][kidx] = aT1;
    g_Tl[chunk][ell + 2][kidx] = aT2;
    g_Tl[chunk][ell + 3][kidx] = aT3;
    g_El[chunk][ell + 0][kidx] = aE0;
    g_El[chunk][ell + 1][kidx] = aE1;
    g_El[chunk][ell + 2][kidx] = aE2;
    g_El[chunk][ell + 3][kidx] = aE3;
}

// ---------------------------------------------------------------------------
// Kernel 2: k-quadrature -> Cl.  48 blocks, 512 threads.
// ---------------------------------------------------------------------------
__global__ __launch_bounds__(512) void spectrum_k2(
    const float* __restrict__ kk_arr,
    const float* __restrict__ Asp,
    const float* __restrict__ nsp,
    float* __restrict__ out)
{
    const int ell = blockIdx.x;
    const int tid = threadIdx.x;

    const float A_s  = Asp[0];
    const float n_s  = nsp[0];
    const float PI_F = 3.14159265358979323846f;
    const float pref = A_s * 2.0f * PI_F * PI_F;

    double tt = 0.0, ee = 0.0, te = 0.0;
    for (int i = tid; i < N_K; i += 512) {
        const float kv = kk_arr[i];
        const float wl = (i == 0)        ? 0.0f : (kv - kk_arr[i - 1]);
        const float wr = (i == N_K - 1)  ? 0.0f : (kk_arr[i + 1] - kv);
        const float pw = exp2f((n_s - 1.0f) * log2f(kv * 20.0f));
        const float weight = 0.5f * (wl + wr) * pref * pw / kv;

        float T = 0.f, E = 0.f;
        #pragma unroll
        for (int c = 0; c < N_CHUNK; ++c) {
            T += g_Tl[c][ell][i];
            E += g_El[c][ell][i];
        }
        tt += (double)(weight * T * T);
        ee += (double)(weight * E * E);
        te += (double)(weight * T * E);
    }

    #pragma unroll
    for (int o = 16; o > 0; o >>= 1) {
        tt += __shfl_down_sync(0xffffffffu, tt, o);
        ee += __shfl_down_sync(0xffffffffu, ee, o);
        te += __shfl_down_sync(0xffffffffu, te, o);
    }
    __shared__ double sT[16], sE[16], sX[16];
    const int wid = tid >> 5, lid = tid & 31;
    if (lid == 0) { sT[wid] = tt; sE[wid] = ee; sX[wid] = te; }
    __syncthreads();
    if (tid < 16) {
        tt = sT[tid]; ee = sE[tid]; te = sX[tid];
        #pragma unroll
        for (int o = 8; o > 0; o >>= 1) {
            tt += __shfl_down_sync(0xffffu, tt, o, 16);
            ee += __shfl_down_sync(0xffffu, ee, o, 16);
            te += __shfl_down_sync(0xffffu, te, o, 16);
        }
        if (tid == 0) {
            const double c = 2.0 / 3.14159265358979323846;
            out[0 * N_ELL + ell] = (float)(c * tt);
            out[1 * N_ELL + ell] = (float)(c * ee);
            out[2 * N_ELL + ell] = (float)(c * te);
        }
    }
}

extern "C" void kernel_launch(void* const* d_in, const int* in_sizes, int n_in,
                              void* d_out, int out_size)
{
    const float* k    = (const float*)d_in[0];
    const float* tau  = (const float*)d_in[1];
    const float* tau0 = (const float*)d_in[2];
    const float* S0   = (const float*)d_in[3];
    const float* S1   = (const float*)d_in[4];
    const float* S2   = (const float*)d_in[5];
    const float* SE   = (const float*)d_in[6];
    const float* bx   = (const float*)d_in[7];
    const float* p0   = (const float*)d_in[8];
    const float* p1   = (const float*)d_in[9];
    const float* p2   = (const float*)d_in[10];
    const float* pe   = (const float*)d_in[11];
    const float* As   = (const float*)d_in[12];
    const float* ns   = (const float*)d_in[13];
    float* out = (float*)d_out;

    pack_tables<<<(N_X * NG + 255) / 256, 256>>>(p0, p1, p2, pe);

    dim3 grid1(N_K / K_PER_BLOCK, N_CHUNK);   // (64, 12)
    dim3 block1(NG, K_PER_BLOCK);             // (12, 16)
    spectrum_k1<<<grid1, block1>>>(k, tau, tau0, S0, S1, S2, SE, bx);

    spectrum_k2<<<N_ELL, 512>>>(k, As, ns, out);
}